// round 1
// baseline (speedup 1.0000x reference)
#include <cuda_runtime.h>

#define EMBED   1024
#define NHEADS  16
#define RANK    32
#define HDIM    64
#define BATCH   2
#define SEQ     2048
#define BSROWS  (BATCH*SEQ)        /* 4096 */
#define QKDIM   (NHEADS*RANK)      /* 512  */
#define SM_SCALE 0.17677669529663687f  /* 1/sqrt(32) */

// Scratch (allocation-free rule: __device__ globals)
__device__ float g_q[BSROWS * QKDIM];
__device__ float g_k[BSROWS * QKDIM];
__device__ float g_v[BSROWS * EMBED];
__device__ float g_attn[BSROWS * EMBED];

// ---------------------------------------------------------------------------
// Generic fp32 GEMM + bias: C[M,N] = A[M,K] @ B[K,N] + bias[N]
// 64x64 block tile, BK=16, 256 threads, 4x4 register microtile.
// ---------------------------------------------------------------------------
__global__ __launch_bounds__(256) void gemm_bias_kernel(
    const float* __restrict__ A, const float* __restrict__ B,
    const float* __restrict__ bias, float* __restrict__ C,
    int M, int N, int K)
{
    __shared__ __align__(16) float As[16][68];   // [k][m]
    __shared__ __align__(16) float Bs[16][68];   // [k][n]

    const int tid = threadIdx.x;
    const int tx = tid & 15;          // n-quadrant
    const int ty = tid >> 4;          // m-quadrant
    const int m0 = blockIdx.y * 64;
    const int n0 = blockIdx.x * 64;

    float acc[4][4];
#pragma unroll
    for (int i = 0; i < 4; i++)
#pragma unroll
        for (int j = 0; j < 4; j++) acc[i][j] = 0.f;

    const int ka = tid & 15;          // A-load k
    const int ma = tid >> 4;          // A-load m base (0..15)
    const int nb = tid & 63;          // B-load n
    const int kb = tid >> 6;          // B-load k base (0..3)

    for (int k0 = 0; k0 < K; k0 += 16) {
#pragma unroll
        for (int it = 0; it < 4; it++) {
            int m = ma + 16 * it;
            As[ka][m] = A[(long)(m0 + m) * K + (k0 + ka)];
            int kk = kb + 4 * it;
            Bs[kk][nb] = B[(long)(k0 + kk) * N + (n0 + nb)];
        }
        __syncthreads();
#pragma unroll
        for (int kk = 0; kk < 16; kk++) {
            float4 av = *reinterpret_cast<const float4*>(&As[kk][ty * 4]);
            float4 bv = *reinterpret_cast<const float4*>(&Bs[kk][tx * 4]);
            float a[4] = {av.x, av.y, av.z, av.w};
            float b[4] = {bv.x, bv.y, bv.z, bv.w};
#pragma unroll
            for (int i = 0; i < 4; i++)
#pragma unroll
                for (int j = 0; j < 4; j++) acc[i][j] += a[i] * b[j];
        }
        __syncthreads();
    }

#pragma unroll
    for (int i = 0; i < 4; i++) {
        int m = m0 + ty * 4 + i;
#pragma unroll
        for (int j = 0; j < 4; j++) {
            int n = n0 + tx * 4 + j;
            C[(long)m * N + n] = acc[i][j] + bias[n];
        }
    }
}

// ---------------------------------------------------------------------------
// Flash attention, fp32. One CTA = one (b, h, 64-row i-tile).
// 256 threads: thread = (row = tid>>2, q = tid&3). Each thread owns 16
// j-columns / d-columns with interleaved mapping col = q*4 + 16*c + i
// (c=0..3, i=0..3) so every smem float4 read is bank-conflict-free.
// ---------------------------------------------------------------------------
__global__ __launch_bounds__(256) void attn_kernel(
    const float* __restrict__ gq, const float* __restrict__ gk,
    const float* __restrict__ gv, float* __restrict__ gout)
{
    __shared__ __align__(16) float Kst[RANK][68];    // [k][j] transposed K tile
    __shared__ __align__(16) float Vs[64][64];       // [j][d]
    __shared__ __align__(16) float PQ[64 * 65];      // Q tile (pitch 32) then P (pitch 65)

    const int tid = threadIdx.x;
    const int row = tid >> 2;       // 0..63 : i-row within tile
    const int q4  = tid & 3;        // quad lane
    const int b  = blockIdx.z;
    const int h  = blockIdx.y;
    const int i0 = blockIdx.x * 64;
    const long bS = (long)b * SEQ;

    // Load Q tile into PQ (pitch 32), then hoist own row into registers
#pragma unroll
    for (int e = 0; e < 8; e++) {
        int flat = e * 256 + tid;
        int r = flat >> 5, c = flat & 31;
        PQ[r * 32 + c] = gq[(bS + i0 + r) * QKDIM + h * RANK + c];
    }
    __syncthreads();
    float qreg[RANK];
#pragma unroll
    for (int k = 0; k < RANK; k++) qreg[k] = PQ[row * 32 + k];
    __syncthreads();   // everyone has read Q before PQ is reused for P

    float m_run = -1e30f, l_run = 0.f;
    float acc[16];
#pragma unroll
    for (int i = 0; i < 16; i++) acc[i] = 0.f;

    for (int j0 = 0; j0 < SEQ; j0 += 64) {
        // K tile transposed: Kst[k][j]
#pragma unroll
        for (int e = 0; e < 8; e++) {
            int flat = e * 256 + tid;
            int r = flat >> 5, c = flat & 31;
            Kst[c][r] = gk[(bS + j0 + r) * QKDIM + h * RANK + c];
        }
        // V tile: Vs[j][d]
#pragma unroll
        for (int e = 0; e < 16; e++) {
            int flat = e * 256 + tid;
            int r = flat >> 6, c = flat & 63;
            Vs[r][c] = gv[(bS + j0 + r) * EMBED + h * HDIM + c];
        }
        __syncthreads();

        // Scores for this thread's 16 j-columns
        float s[16];
#pragma unroll
        for (int i = 0; i < 16; i++) s[i] = 0.f;
#pragma unroll
        for (int k = 0; k < RANK; k++) {
            float qk = qreg[k];
#pragma unroll
            for (int c = 0; c < 4; c++) {
                float4 kv = *reinterpret_cast<const float4*>(&Kst[k][q4 * 4 + 16 * c]);
                s[c * 4 + 0] += qk * kv.x;
                s[c * 4 + 1] += qk * kv.y;
                s[c * 4 + 2] += qk * kv.z;
                s[c * 4 + 3] += qk * kv.w;
            }
        }
        float tmax = -1e30f;
#pragma unroll
        for (int i = 0; i < 16; i++) { s[i] *= SM_SCALE; tmax = fmaxf(tmax, s[i]); }
        // row max across the quad (lanes differ in bits 0,1)
        tmax = fmaxf(tmax, __shfl_xor_sync(0xffffffffu, tmax, 1));
        tmax = fmaxf(tmax, __shfl_xor_sync(0xffffffffu, tmax, 2));
        float mnew = fmaxf(m_run, tmax);
        float corr = __expf(m_run - mnew);
        float tsum = 0.f;
#pragma unroll
        for (int c = 0; c < 4; c++)
#pragma unroll
            for (int i = 0; i < 4; i++) {
                float p = __expf(s[c * 4 + i] - mnew);
                tsum += p;
                PQ[row * 65 + q4 * 4 + 16 * c + i] = p;   // P exchange (quad-local)
            }
        tsum += __shfl_xor_sync(0xffffffffu, tsum, 1);
        tsum += __shfl_xor_sync(0xffffffffu, tsum, 2);
        l_run = l_run * corr + tsum;
        m_run = mnew;
#pragma unroll
        for (int i = 0; i < 16; i++) acc[i] *= corr;
        __syncwarp();   // P produced/consumed within the same quad (same warp)

        // PV: acc[d] += sum_j P[row][j] * V[j][d]
#pragma unroll 8
        for (int j = 0; j < 64; j++) {
            float pj = PQ[row * 65 + j];
#pragma unroll
            for (int c = 0; c < 4; c++) {
                float4 v = *reinterpret_cast<const float4*>(&Vs[j][q4 * 4 + 16 * c]);
                acc[c * 4 + 0] += pj * v.x;
                acc[c * 4 + 1] += pj * v.y;
                acc[c * 4 + 2] += pj * v.z;
                acc[c * 4 + 3] += pj * v.w;
            }
        }
        __syncthreads();   // done with Kst/Vs (and P) before next tile load
    }

    float inv = 1.f / l_run;
#pragma unroll
    for (int c = 0; c < 4; c++) {
        float4 o;
        o.x = acc[c * 4 + 0] * inv;
        o.y = acc[c * 4 + 1] * inv;
        o.z = acc[c * 4 + 2] * inv;
        o.w = acc[c * 4 + 3] * inv;
        *reinterpret_cast<float4*>(
            &gout[(bS + i0 + row) * EMBED + h * HDIM + q4 * 4 + 16 * c]) = o;
    }
}

// ---------------------------------------------------------------------------
extern "C" void kernel_launch(void* const* d_in, const int* in_sizes, int n_in,
                              void* d_out, int out_size)
{
    const float* X  = (const float*)d_in[0];
    const float* Wq = (const float*)d_in[1];
    const float* bq = (const float*)d_in[2];
    const float* Wk = (const float*)d_in[3];
    const float* bk = (const float*)d_in[4];
    const float* Wv = (const float*)d_in[5];
    const float* bv = (const float*)d_in[6];
    const float* Wo = (const float*)d_in[7];
    const float* bo = (const float*)d_in[8];
    float* out = (float*)d_out;

    float *pq, *pk, *pv, *pa;
    cudaGetSymbolAddress((void**)&pq, g_q);
    cudaGetSymbolAddress((void**)&pk, g_k);
    cudaGetSymbolAddress((void**)&pv, g_v);
    cudaGetSymbolAddress((void**)&pa, g_attn);

    dim3 blk(256);
    // Projections
    gemm_bias_kernel<<<dim3(QKDIM / 64, BSROWS / 64), blk>>>(X, Wq, bq, pq, BSROWS, QKDIM, EMBED);
    gemm_bias_kernel<<<dim3(QKDIM / 64, BSROWS / 64), blk>>>(X, Wk, bk, pk, BSROWS, QKDIM, EMBED);
    gemm_bias_kernel<<<dim3(EMBED / 64, BSROWS / 64), blk>>>(X, Wv, bv, pv, BSROWS, EMBED, EMBED);
    // Attention
    attn_kernel<<<dim3(SEQ / 64, NHEADS, BATCH), blk>>>(pq, pk, pv, pa);
    // Output projection
    gemm_bias_kernel<<<dim3(EMBED / 64, BSROWS / 64), blk>>>(pa, Wo, bo, out, BSROWS, EMBED, EMBED);
}

// round 5
// speedup vs baseline: 2.2008x; 2.2008x over previous
#include <cuda_runtime.h>
#include <cstdint>

#define EMBED   1024
#define NHEADS  16
#define RANK    32
#define HDIM    64
#define BATCH   2
#define SEQ     2048
#define BSROWS  (BATCH*SEQ)        /* 4096 */
#define QKDIM   (NHEADS*RANK)      /* 512  */
#define NPAIRS  (BATCH*NHEADS)     /* 32   */
#define SM_SCALE 0.17677669529663687f

// ---------------- scratch (__device__ globals: allocation-free rule) --------
__device__ float g_q   [BSROWS * QKDIM];
__device__ float g_k   [BSROWS * QKDIM];
__device__ float g_v   [BSROWS * EMBED];
__device__ float g_attn[BSROWS * EMBED];
__device__ float g_vT  [NPAIRS * HDIM * SEQ];
__device__ float g_s   [(size_t)NPAIRS * SEQ * SEQ];     // 512 MB
__device__ float g_mx  [NPAIRS * SEQ];
__device__ float g_li  [NPAIRS * SEQ];
__device__ float g_wqT [QKDIM * EMBED];
__device__ float g_wkT [QKDIM * EMBED];
__device__ float g_wvT [EMBED * EMBED];
__device__ float g_woT [EMBED * EMBED];

// ---------------- m16n8k8 tf32 mma ------------------------------------------
__device__ __forceinline__ void mma_tf32(float& c0, float& c1, float& c2, float& c3,
                                         uint32_t a0, uint32_t a1, uint32_t a2, uint32_t a3,
                                         uint32_t b0, uint32_t b1)
{
    asm volatile(
        "mma.sync.aligned.m16n8k8.row.col.f32.tf32.tf32.f32 "
        "{%0,%1,%2,%3}, {%4,%5,%6,%7}, {%8,%9}, {%0,%1,%2,%3};"
        : "+f"(c0), "+f"(c1), "+f"(c2), "+f"(c3)
        : "r"(a0), "r"(a1), "r"(a2), "r"(a3), "r"(b0), "r"(b1));
}

// lo residual: v - trunc_to_tf32(v).  (tf32 MMA operand reads bits[31:13],
// so passing the raw fp32 register acts as the truncated hi part.)
__device__ __forceinline__ uint32_t tf32_lo(float v)
{
    float hi = __uint_as_float(__float_as_uint(v) & 0xFFFFE000u);
    return __float_as_uint(v - hi);
}

// ---------------- generic tf32x3 HMMA GEMM -----------------------------------
// C[m][n] = rowscale[m] * uscale * ( sum_k A[m][k]*B[n][k] + bias[n] )
// A: [M,K] row-major; B: [N,K] row-major (k-major — mma "col" operand).
// Tile: 128 x NT, K-tile 32. 256 threads = 8 warps.
// Split-precision: acc += Ahi*Bhi + Alo*Bhi + Ahi*Blo  (near-fp32 accuracy).
// If TEXP: a = exp(a_raw - mvec[row]).
// Batched via blockIdx.z: offsets off = OffB*(z>>4) + OffH*(z&15).
template<int NT, bool TEXP>
__global__ __launch_bounds__(256, 2) void tc_gemm(
    const float* __restrict__ A, long aOffB, long aOffH, int lda,
    const float* __restrict__ B, long bOffB, long bOffH, int ldb,
    float* __restrict__ C, long cOffB, long cOffH, int ldc,
    int K,
    const float* __restrict__ bias,
    const float* __restrict__ rowscale, long rsZ,
    const float* __restrict__ mvec, long mvZ,
    float uscale)
{
    constexpr int PITCH = 36;                 // floats per smem row (conflict-free frags)
    constexpr int MF = (NT == 128) ? 4 : 2;   // 16-row m-frags per warp
    __shared__ __align__(16) float As[128][PITCH];
    __shared__ __align__(16) float Bs[NT][PITCH];

    const int tid  = threadIdx.x;
    const int wid  = tid >> 5;
    const int lane = tid & 31;
    const int g    = lane >> 2;       // groupID (row within frag)
    const int tg   = lane & 3;        // thread-in-group (k/col idx)
    const int z  = blockIdx.z, zb = z >> 4, zh = z & 15;
    const int m0 = blockIdx.y * 128, n0 = blockIdx.x * NT;

    const int warpM = (NT == 128) ? (wid >> 2) * 64 : (wid >> 1) * 32;
    const int warpN = (NT == 128) ? (wid & 3) * 32  : (wid & 1) * 32;

    const float* Ab = A + aOffB * zb + aOffH * zh;
    const float* Bb = B + bOffB * zb + bOffH * zh;
    float*       Cb = C + cOffB * zb + cOffH * zh;

    // A-tile load mapping: one row per thread-pair
    const int ar = tid >> 1;              // 0..127
    const int ah = (tid & 1) * 16;        // col base
    float mrow = 0.f;
    if (TEXP) mrow = mvec[mvZ * (long)z + m0 + ar];

    float acc[MF][4][4];
#pragma unroll
    for (int i = 0; i < MF; i++)
#pragma unroll
        for (int j = 0; j < 4; j++)
#pragma unroll
            for (int r = 0; r < 4; r++) acc[i][j][r] = 0.f;

    const int nk = K >> 5;
    for (int kt = 0; kt < nk; kt++) {
        const int k0 = kt << 5;
        // ---- A tile: 128 x 32 ----
        {
            const float* src = Ab + (size_t)(m0 + ar) * lda + k0 + ah;
#pragma unroll
            for (int c = 0; c < 4; c++) {
                float4 v = *reinterpret_cast<const float4*>(src + c * 4);
                if (TEXP) {
                    v.x = __expf(v.x - mrow); v.y = __expf(v.y - mrow);
                    v.z = __expf(v.z - mrow); v.w = __expf(v.w - mrow);
                }
                *reinterpret_cast<float4*>(&As[ar][ah + c * 4]) = v;
            }
        }
        // ---- B tile: NT x 32 ----
        if (NT == 128) {
            const float* src = Bb + (size_t)(n0 + ar) * ldb + k0 + ah;
#pragma unroll
            for (int c = 0; c < 4; c++)
                *reinterpret_cast<float4*>(&Bs[ar][ah + c * 4]) =
                    *reinterpret_cast<const float4*>(src + c * 4);
        } else {
            const int br = tid >> 2;            // 0..63
            const int bh = (tid & 3) * 8;
            const float* src = Bb + (size_t)(n0 + br) * ldb + k0 + bh;
#pragma unroll
            for (int c = 0; c < 2; c++)
                *reinterpret_cast<float4*>(&Bs[br][bh + c * 4]) =
                    *reinterpret_cast<const float4*>(src + c * 4);
        }
        __syncthreads();

        // ---- compute: 4 k-steps of 8, tf32x3 split ----
#pragma unroll
        for (int ks = 0; ks < 4; ks++) {
            const int kb = ks * 8;
            uint32_t ahi[MF][4], alo[MF][4];
#pragma unroll
            for (int i = 0; i < MF; i++) {
                const int r = warpM + i * 16 + g;
                float v0 = As[r    ][kb + tg    ];
                float v1 = As[r + 8][kb + tg    ];
                float v2 = As[r    ][kb + tg + 4];
                float v3 = As[r + 8][kb + tg + 4];
                ahi[i][0] = __float_as_uint(v0); alo[i][0] = tf32_lo(v0);
                ahi[i][1] = __float_as_uint(v1); alo[i][1] = tf32_lo(v1);
                ahi[i][2] = __float_as_uint(v2); alo[i][2] = tf32_lo(v2);
                ahi[i][3] = __float_as_uint(v3); alo[i][3] = tf32_lo(v3);
            }
#pragma unroll
            for (int j = 0; j < 4; j++) {
                const int n = warpN + j * 8 + g;
                float b0 = Bs[n][kb + tg    ];
                float b1 = Bs[n][kb + tg + 4];
                uint32_t bh0 = __float_as_uint(b0), bh1 = __float_as_uint(b1);
                uint32_t bl0 = tf32_lo(b0),         bl1 = tf32_lo(b1);
#pragma unroll
                for (int i = 0; i < MF; i++) {
                    mma_tf32(acc[i][j][0], acc[i][j][1], acc[i][j][2], acc[i][j][3],
                             ahi[i][0], ahi[i][1], ahi[i][2], ahi[i][3], bh0, bh1);
                    mma_tf32(acc[i][j][0], acc[i][j][1], acc[i][j][2], acc[i][j][3],
                             alo[i][0], alo[i][1], alo[i][2], alo[i][3], bh0, bh1);
                    mma_tf32(acc[i][j][0], acc[i][j][1], acc[i][j][2], acc[i][j][3],
                             ahi[i][0], ahi[i][1], ahi[i][2], ahi[i][3], bl0, bl1);
                }
            }
        }
        __syncthreads();
    }

    // ---- epilogue ----
#pragma unroll
    for (int i = 0; i < MF; i++) {
        const int r0 = m0 + warpM + i * 16 + g;
        const int r1 = r0 + 8;
        float rs0 = uscale, rs1 = uscale;
        if (rowscale) {
            rs0 *= rowscale[rsZ * (long)z + r0];
            rs1 *= rowscale[rsZ * (long)z + r1];
        }
#pragma unroll
        for (int j = 0; j < 4; j++) {
            const int col = n0 + warpN + j * 8 + 2 * tg;
            float b0 = 0.f, b1 = 0.f;
            if (bias) { b0 = bias[col]; b1 = bias[col + 1]; }
            float2 o0, o1;
            o0.x = (acc[i][j][0] + b0) * rs0;
            o0.y = (acc[i][j][1] + b1) * rs0;
            o1.x = (acc[i][j][2] + b0) * rs1;
            o1.y = (acc[i][j][3] + b1) * rs1;
            *reinterpret_cast<float2*>(Cb + (size_t)r0 * ldc + col) = o0;
            *reinterpret_cast<float2*>(Cb + (size_t)r1 * ldc + col) = o1;
        }
    }
}

// ---------------- softmax row stats: max + 1/sum(exp) -----------------------
__global__ __launch_bounds__(256) void softmax_stats(
    const float* __restrict__ S, float* __restrict__ mx, float* __restrict__ linv)
{
    const int warp = threadIdx.x >> 5, lane = threadIdx.x & 31;
    const size_t R = (size_t)blockIdx.x * 8 + warp;
    const float* s = S + R * SEQ;
    float v[64];
#pragma unroll
    for (int it = 0; it < 16; it++) {
        float4 t = *reinterpret_cast<const float4*>(s + (size_t)(it * 32 + lane) * 4);
        v[it * 4 + 0] = t.x; v[it * 4 + 1] = t.y; v[it * 4 + 2] = t.z; v[it * 4 + 3] = t.w;
    }
    float m = -1e30f;
#pragma unroll
    for (int i = 0; i < 64; i++) m = fmaxf(m, v[i]);
#pragma unroll
    for (int o = 16; o > 0; o >>= 1) m = fmaxf(m, __shfl_xor_sync(0xffffffffu, m, o));
    float sum = 0.f;
#pragma unroll
    for (int i = 0; i < 64; i++) sum += __expf(v[i] - m);
#pragma unroll
    for (int o = 16; o > 0; o >>= 1) sum += __shfl_xor_sync(0xffffffffu, sum, o);
    if (lane == 0) { mx[R] = m; linv[R] = 1.f / sum; }
}

// ---------------- transposes -------------------------------------------------
__global__ void transpose_w(const float* __restrict__ in, float* __restrict__ out,
                            int R, int C)
{
    __shared__ float t[32][33];
    const int c0 = blockIdx.x * 32, r0 = blockIdx.y * 32;
    const int x = threadIdx.x, y = threadIdx.y;
#pragma unroll
    for (int i = 0; i < 32; i += 8) t[y + i][x] = in[(size_t)(r0 + y + i) * C + c0 + x];
    __syncthreads();
#pragma unroll
    for (int i = 0; i < 32; i += 8) out[(size_t)(c0 + y + i) * R + r0 + x] = t[x][y + i];
}

// gvT[pair][d][j] = V[(b*SEQ+j)*EMBED + h*HDIM + d]
__global__ void transpose_v(const float* __restrict__ v, float* __restrict__ vt)
{
    __shared__ float t[32][33];
    const int z = blockIdx.z, zb = z >> 4, zh = z & 15;
    const int j0 = blockIdx.x * 32, d0 = blockIdx.y * 32;
    const int x = threadIdx.x, y = threadIdx.y;
    const float* in = v + (size_t)zb * SEQ * EMBED + (size_t)zh * HDIM;
    float* out = vt + (size_t)z * HDIM * SEQ;
#pragma unroll
    for (int i = 0; i < 32; i += 8) t[y + i][x] = in[(size_t)(j0 + y + i) * EMBED + d0 + x];
    __syncthreads();
#pragma unroll
    for (int i = 0; i < 32; i += 8) out[(size_t)(d0 + y + i) * SEQ + j0 + x] = t[x][y + i];
}

// ---------------- launch ------------------------------------------------------
extern "C" void kernel_launch(void* const* d_in, const int* in_sizes, int n_in,
                              void* d_out, int out_size)
{
    const float* X  = (const float*)d_in[0];
    const float* Wq = (const float*)d_in[1];
    const float* bq = (const float*)d_in[2];
    const float* Wk = (const float*)d_in[3];
    const float* bk = (const float*)d_in[4];
    const float* Wv = (const float*)d_in[5];
    const float* bv = (const float*)d_in[6];
    const float* Wo = (const float*)d_in[7];
    const float* bo = (const float*)d_in[8];
    float* out = (float*)d_out;

    float *pq, *pk, *pv, *pa, *pvT, *ps, *pmx, *pli, *pwqT, *pwkT, *pwvT, *pwoT;
    cudaGetSymbolAddress((void**)&pq,   g_q);
    cudaGetSymbolAddress((void**)&pk,   g_k);
    cudaGetSymbolAddress((void**)&pv,   g_v);
    cudaGetSymbolAddress((void**)&pa,   g_attn);
    cudaGetSymbolAddress((void**)&pvT,  g_vT);
    cudaGetSymbolAddress((void**)&ps,   g_s);
    cudaGetSymbolAddress((void**)&pmx,  g_mx);
    cudaGetSymbolAddress((void**)&pli,  g_li);
    cudaGetSymbolAddress((void**)&pwqT, g_wqT);
    cudaGetSymbolAddress((void**)&pwkT, g_wkT);
    cudaGetSymbolAddress((void**)&pwvT, g_wvT);
    cudaGetSymbolAddress((void**)&pwoT, g_woT);

    const dim3 tb(32, 8);
    transpose_w<<<dim3(QKDIM / 32, EMBED / 32), tb>>>(Wq, pwqT, EMBED, QKDIM);
    transpose_w<<<dim3(QKDIM / 32, EMBED / 32), tb>>>(Wk, pwkT, EMBED, QKDIM);
    transpose_w<<<dim3(EMBED / 32, EMBED / 32), tb>>>(Wv, pwvT, EMBED, EMBED);
    transpose_w<<<dim3(EMBED / 32, EMBED / 32), tb>>>(Wo, pwoT, EMBED, EMBED);

    const long SS = (long)SEQ * SEQ;

    // Q/K/V projections (SM_SCALE folded into Q)
    tc_gemm<128, false><<<dim3(QKDIM / 128, BSROWS / 128, 1), 256>>>(
        X, 0, 0, EMBED, pwqT, 0, 0, EMBED, pq, 0, 0, QKDIM, EMBED,
        bq, nullptr, 0, nullptr, 0, SM_SCALE);
    tc_gemm<128, false><<<dim3(QKDIM / 128, BSROWS / 128, 1), 256>>>(
        X, 0, 0, EMBED, pwkT, 0, 0, EMBED, pk, 0, 0, QKDIM, EMBED,
        bk, nullptr, 0, nullptr, 0, 1.f);
    tc_gemm<128, false><<<dim3(EMBED / 128, BSROWS / 128, 1), 256>>>(
        X, 0, 0, EMBED, pwvT, 0, 0, EMBED, pv, 0, 0, EMBED, EMBED,
        bv, nullptr, 0, nullptr, 0, 1.f);

    transpose_v<<<dim3(SEQ / 32, HDIM / 32, NPAIRS), tb>>>(pv, pvT);

    // S = (s*Q) K^T per (b,h) pair
    tc_gemm<128, false><<<dim3(SEQ / 128, SEQ / 128, NPAIRS), 256>>>(
        pq, (long)SEQ * QKDIM, RANK, QKDIM,
        pk, (long)SEQ * QKDIM, RANK, QKDIM,
        ps, 16 * SS, SS, SEQ,
        RANK, nullptr, nullptr, 0, nullptr, 0, 1.f);

    softmax_stats<<<(NPAIRS * SEQ) / 8, 256>>>(ps, pmx, pli);

    // O = softmax(S) V : exp applied in A-load, 1/l in epilogue
    tc_gemm<64, true><<<dim3(1, SEQ / 128, NPAIRS), 256>>>(
        ps, 16 * SS, SS, SEQ,
        pvT, (long)16 * HDIM * SEQ, (long)HDIM * SEQ, SEQ,
        pa, (long)SEQ * EMBED, HDIM, EMBED,
        SEQ, nullptr, pli, SEQ, pmx, SEQ, 1.f);

    // final projection
    tc_gemm<128, false><<<dim3(EMBED / 128, BSROWS / 128, 1), 256>>>(
        pa, 0, 0, EMBED, pwoT, 0, 0, EMBED, out, 0, 0, EMBED, EMBED,
        bo, nullptr, 0, nullptr, 0, 1.f);
}

// round 6
// speedup vs baseline: 2.5670x; 1.1664x over previous
#include <cuda_runtime.h>
#include <cstdint>

#define EMBED   1024
#define NHEADS  16
#define RANK    32
#define HDIM    64
#define BATCH   2
#define SEQ     2048
#define BSROWS  (BATCH*SEQ)        /* 4096 */
#define QKDIM   (NHEADS*RANK)      /* 512  */
#define NPAIRS  (BATCH*NHEADS)     /* 32   */
#define SM_SCALE 0.17677669529663687f

// ---------------- scratch (__device__ globals: allocation-free rule) --------
__device__ float g_q   [BSROWS * QKDIM];
__device__ float g_k   [BSROWS * QKDIM];
__device__ float g_v   [BSROWS * EMBED];
__device__ float g_attn[BSROWS * EMBED];
__device__ float g_vT  [NPAIRS * HDIM * SEQ];
__device__ float g_wqT [QKDIM * EMBED];
__device__ float g_wkT [QKDIM * EMBED];
__device__ float g_wvT [EMBED * EMBED];
__device__ float g_woT [EMBED * EMBED];

// ---------------- m16n8k8 tf32 mma ------------------------------------------
__device__ __forceinline__ void mma_tf32(float& c0, float& c1, float& c2, float& c3,
                                         uint32_t a0, uint32_t a1, uint32_t a2, uint32_t a3,
                                         uint32_t b0, uint32_t b1)
{
    asm volatile(
        "mma.sync.aligned.m16n8k8.row.col.f32.tf32.tf32.f32 "
        "{%0,%1,%2,%3}, {%4,%5,%6,%7}, {%8,%9}, {%0,%1,%2,%3};"
        : "+f"(c0), "+f"(c1), "+f"(c2), "+f"(c3)
        : "r"(a0), "r"(a1), "r"(a2), "r"(a3), "r"(b0), "r"(b1));
}

// lo residual: v - trunc_to_tf32(v).
__device__ __forceinline__ uint32_t tf32_lo(float v)
{
    float hi = __uint_as_float(__float_as_uint(v) & 0xFFFFE000u);
    return __float_as_uint(v - hi);
}

// ---------------- cp.async helpers ------------------------------------------
__device__ __forceinline__ uint32_t smem_u32(const void* p) {
    uint32_t a;
    asm("{ .reg .u64 t; cvta.to.shared.u64 t, %1; cvt.u32.u64 %0, t; }" : "=r"(a) : "l"(p));
    return a;
}
__device__ __forceinline__ void cp16(uint32_t dst, const void* src) {
    asm volatile("cp.async.cg.shared.global [%0], [%1], 16;" :: "r"(dst), "l"(src));
}
#define CP_COMMIT() asm volatile("cp.async.commit_group;" ::: "memory")
#define CP_WAIT(n)  asm volatile("cp.async.wait_group %0;" :: "n"(n) : "memory")

// ---------------- generic tf32x3 HMMA GEMM (projections) ---------------------
// C[m][n] = uscale * ( sum_k A[m][k]*B[n][k] + bias[n] )
// A: [M,K] row-major; B: [N,K] row-major. Tile 128x128, K-tile 32, 256 thr.
__global__ __launch_bounds__(256, 2) void tc_gemm(
    const float* __restrict__ A, int lda,
    const float* __restrict__ B, int ldb,
    float* __restrict__ C, int ldc,
    int K, const float* __restrict__ bias, float uscale)
{
    constexpr int PITCH = 36;
    __shared__ __align__(16) float As[128][PITCH];
    __shared__ __align__(16) float Bs[128][PITCH];

    const int tid  = threadIdx.x;
    const int wid  = tid >> 5;
    const int lane = tid & 31;
    const int g    = lane >> 2;
    const int tg   = lane & 3;
    const int m0 = blockIdx.y * 128, n0 = blockIdx.x * 128;
    const int warpM = (wid >> 2) * 64;
    const int warpN = (wid & 3) * 32;

    const int ar = tid >> 1;
    const int ah = (tid & 1) * 16;

    float acc[4][4][4];
#pragma unroll
    for (int i = 0; i < 4; i++)
#pragma unroll
        for (int j = 0; j < 4; j++)
#pragma unroll
            for (int r = 0; r < 4; r++) acc[i][j][r] = 0.f;

    const int nk = K >> 5;
    for (int kt = 0; kt < nk; kt++) {
        const int k0 = kt << 5;
        {
            const float* src = A + (size_t)(m0 + ar) * lda + k0 + ah;
#pragma unroll
            for (int c = 0; c < 4; c++)
                *reinterpret_cast<float4*>(&As[ar][ah + c * 4]) =
                    *reinterpret_cast<const float4*>(src + c * 4);
        }
        {
            const float* src = B + (size_t)(n0 + ar) * ldb + k0 + ah;
#pragma unroll
            for (int c = 0; c < 4; c++)
                *reinterpret_cast<float4*>(&Bs[ar][ah + c * 4]) =
                    *reinterpret_cast<const float4*>(src + c * 4);
        }
        __syncthreads();
#pragma unroll
        for (int ks = 0; ks < 4; ks++) {
            const int kb = ks * 8;
            uint32_t ahi[4][4], alo[4][4];
#pragma unroll
            for (int i = 0; i < 4; i++) {
                const int r = warpM + i * 16 + g;
                float v0 = As[r    ][kb + tg    ];
                float v1 = As[r + 8][kb + tg    ];
                float v2 = As[r    ][kb + tg + 4];
                float v3 = As[r + 8][kb + tg + 4];
                ahi[i][0] = __float_as_uint(v0); alo[i][0] = tf32_lo(v0);
                ahi[i][1] = __float_as_uint(v1); alo[i][1] = tf32_lo(v1);
                ahi[i][2] = __float_as_uint(v2); alo[i][2] = tf32_lo(v2);
                ahi[i][3] = __float_as_uint(v3); alo[i][3] = tf32_lo(v3);
            }
#pragma unroll
            for (int j = 0; j < 4; j++) {
                const int n = warpN + j * 8 + g;
                float b0 = Bs[n][kb + tg    ];
                float b1 = Bs[n][kb + tg + 4];
                uint32_t bh0 = __float_as_uint(b0), bh1 = __float_as_uint(b1);
                uint32_t bl0 = tf32_lo(b0),         bl1 = tf32_lo(b1);
#pragma unroll
                for (int i = 0; i < 4; i++) {
                    mma_tf32(acc[i][j][0], acc[i][j][1], acc[i][j][2], acc[i][j][3],
                             ahi[i][0], ahi[i][1], ahi[i][2], ahi[i][3], bh0, bh1);
                    mma_tf32(acc[i][j][0], acc[i][j][1], acc[i][j][2], acc[i][j][3],
                             alo[i][0], alo[i][1], alo[i][2], alo[i][3], bh0, bh1);
                    mma_tf32(acc[i][j][0], acc[i][j][1], acc[i][j][2], acc[i][j][3],
                             ahi[i][0], ahi[i][1], ahi[i][2], ahi[i][3], bl0, bl1);
                }
            }
        }
        __syncthreads();
    }

#pragma unroll
    for (int i = 0; i < 4; i++) {
        const int r0 = m0 + warpM + i * 16 + g;
        const int r1 = r0 + 8;
#pragma unroll
        for (int j = 0; j < 4; j++) {
            const int col = n0 + warpN + j * 8 + 2 * tg;
            float b0 = bias ? bias[col] : 0.f;
            float b1 = bias ? bias[col + 1] : 0.f;
            float2 o0, o1;
            o0.x = (acc[i][j][0] + b0) * uscale;
            o0.y = (acc[i][j][1] + b1) * uscale;
            o1.x = (acc[i][j][2] + b0) * uscale;
            o1.y = (acc[i][j][3] + b1) * uscale;
            *reinterpret_cast<float2*>(C + (size_t)r0 * ldc + col) = o0;
            *reinterpret_cast<float2*>(C + (size_t)r1 * ldc + col) = o1;
        }
    }
}

// ---------------- fused flash attention (tf32x3) -----------------------------
// Grid (SEQ/128, NPAIRS). 256 threads = 8 warps; warp w owns rows w*16..w*16+15
// of the 128-row i-tile, across all 128 j-cols. Online softmax per row.
// Smem: K tiles [2][128][36], Vt tiles [2][64][132], cp.async double-buffered.
#define KS_PITCH 36
#define VT_PITCH 132
#define KS_BUFB  (128 * KS_PITCH * 4)       /* 18432 B */
#define VT_BUFB  (64 * VT_PITCH * 4)        /* 33792 B */
#define FLASH_SMEM (2 * KS_BUFB + 2 * VT_BUFB)   /* 104448 B */

__global__ __launch_bounds__(256, 1) void flash_kernel(
    const float* __restrict__ gq, const float* __restrict__ gk,
    const float* __restrict__ gvT, float* __restrict__ gout)
{
    extern __shared__ char sm[];
    const uint32_t sb = smem_u32(sm);
    float* KsF  = reinterpret_cast<float*>(sm);
    float* VtF  = reinterpret_cast<float*>(sm + 2 * KS_BUFB);

    const int tid  = threadIdx.x;
    const int wid  = tid >> 5;
    const int lane = tid & 31;
    const int g    = lane >> 2;
    const int tg   = lane & 3;
    const int z  = blockIdx.y, zb = z >> 4, zh = z & 15;
    const int i0 = blockIdx.x * 128;
    const long bS = (long)zb * SEQ;
    const int hq = zh * RANK;
    const size_t vbase = (size_t)z * HDIM * SEQ;
    const int warpM = wid * 16;

    // ---- Q fragments (resident, scale folded before split) ----
    uint32_t qhi[4][4], qlo[4][4];
    {
        const float* q0 = gq + (size_t)(bS + i0 + warpM + g) * QKDIM + hq;
        const float* q1 = q0 + 8 * QKDIM;
#pragma unroll
        for (int ks = 0; ks < 4; ks++) {
            float v0 = q0[ks * 8 + tg    ] * SM_SCALE;
            float v1 = q1[ks * 8 + tg    ] * SM_SCALE;
            float v2 = q0[ks * 8 + tg + 4] * SM_SCALE;
            float v3 = q1[ks * 8 + tg + 4] * SM_SCALE;
            qhi[ks][0] = __float_as_uint(v0); qlo[ks][0] = tf32_lo(v0);
            qhi[ks][1] = __float_as_uint(v1); qlo[ks][1] = tf32_lo(v1);
            qhi[ks][2] = __float_as_uint(v2); qlo[ks][2] = tf32_lo(v2);
            qhi[ks][3] = __float_as_uint(v3); qlo[ks][3] = tf32_lo(v3);
        }
    }

    // ---- tile loader (cp.async) ----
    auto load_tiles = [&](int buf, int j0) {
        // K tile: 128 rows x 32 floats = 1024 16B-chunks
#pragma unroll
        for (int t = 0; t < 4; t++) {
            int c = tid + t * 256;
            int row = c >> 3, c16 = c & 7;
            uint32_t dst = sb + buf * KS_BUFB + row * (KS_PITCH * 4) + c16 * 16;
            cp16(dst, gk + (size_t)(bS + j0 + row) * QKDIM + hq + c16 * 4);
        }
        // Vt tile: 64 rows x 128 floats = 2048 chunks
#pragma unroll
        for (int t = 0; t < 8; t++) {
            int c = tid + t * 256;
            int d = c >> 5, c16 = c & 31;
            uint32_t dst = sb + 2 * KS_BUFB + buf * VT_BUFB + d * (VT_PITCH * 4) + c16 * 16;
            cp16(dst, gvT + vbase + (size_t)d * SEQ + j0 + c16 * 4);
        }
        CP_COMMIT();
    };

    float o[8][4];
#pragma unroll
    for (int nf = 0; nf < 8; nf++)
#pragma unroll
        for (int r = 0; r < 4; r++) o[nf][r] = 0.f;
    float m0r = -1e30f, m1r = -1e30f, l0 = 0.f, l1 = 0.f;

    load_tiles(0, 0);

    for (int jt = 0; jt < 16; jt++) {
        if (jt < 15) load_tiles((jt + 1) & 1, (jt + 1) * 128);
        if (jt < 15) { CP_WAIT(1); } else { CP_WAIT(0); }
        __syncthreads();

        const float* K  = KsF + (jt & 1) * (KS_BUFB / 4);
        const float* VT = VtF + (jt & 1) * (VT_BUFB / 4);

        // ---- S = Q K^T (tf32x3) ----
        float p[16][4];
#pragma unroll
        for (int jf = 0; jf < 16; jf++)
#pragma unroll
            for (int r = 0; r < 4; r++) p[jf][r] = 0.f;

#pragma unroll
        for (int ks = 0; ks < 4; ks++) {
            const int kb = ks * 8;
#pragma unroll
            for (int jf = 0; jf < 16; jf++) {
                const int n = jf * 8 + g;
                float b0 = K[n * KS_PITCH + kb + tg    ];
                float b1 = K[n * KS_PITCH + kb + tg + 4];
                uint32_t bh0 = __float_as_uint(b0), bh1 = __float_as_uint(b1);
                uint32_t bl0 = tf32_lo(b0),         bl1 = tf32_lo(b1);
                mma_tf32(p[jf][0], p[jf][1], p[jf][2], p[jf][3],
                         qhi[ks][0], qhi[ks][1], qhi[ks][2], qhi[ks][3], bh0, bh1);
                mma_tf32(p[jf][0], p[jf][1], p[jf][2], p[jf][3],
                         qlo[ks][0], qlo[ks][1], qlo[ks][2], qlo[ks][3], bh0, bh1);
                mma_tf32(p[jf][0], p[jf][1], p[jf][2], p[jf][3],
                         qhi[ks][0], qhi[ks][1], qhi[ks][2], qhi[ks][3], bl0, bl1);
            }
        }

        // ---- online softmax (rows g and g+8) ----
        float mx0 = -1e30f, mx1 = -1e30f;
#pragma unroll
        for (int jf = 0; jf < 16; jf++) {
            mx0 = fmaxf(mx0, fmaxf(p[jf][0], p[jf][1]));
            mx1 = fmaxf(mx1, fmaxf(p[jf][2], p[jf][3]));
        }
        mx0 = fmaxf(mx0, __shfl_xor_sync(0xffffffffu, mx0, 1));
        mx0 = fmaxf(mx0, __shfl_xor_sync(0xffffffffu, mx0, 2));
        mx1 = fmaxf(mx1, __shfl_xor_sync(0xffffffffu, mx1, 1));
        mx1 = fmaxf(mx1, __shfl_xor_sync(0xffffffffu, mx1, 2));
        float mn0 = fmaxf(m0r, mx0), mn1 = fmaxf(m1r, mx1);
        float c0 = __expf(m0r - mn0), c1 = __expf(m1r - mn1);
        float s0 = 0.f, s1 = 0.f;
#pragma unroll
        for (int jf = 0; jf < 16; jf++) {
            p[jf][0] = __expf(p[jf][0] - mn0); s0 += p[jf][0];
            p[jf][1] = __expf(p[jf][1] - mn0); s0 += p[jf][1];
            p[jf][2] = __expf(p[jf][2] - mn1); s1 += p[jf][2];
            p[jf][3] = __expf(p[jf][3] - mn1); s1 += p[jf][3];
        }
        s0 += __shfl_xor_sync(0xffffffffu, s0, 1);
        s0 += __shfl_xor_sync(0xffffffffu, s0, 2);
        s1 += __shfl_xor_sync(0xffffffffu, s1, 1);
        s1 += __shfl_xor_sync(0xffffffffu, s1, 2);
        l0 = l0 * c0 + s0; l1 = l1 * c1 + s1;
        m0r = mn0; m1r = mn1;
#pragma unroll
        for (int nf = 0; nf < 8; nf++) {
            o[nf][0] *= c0; o[nf][1] *= c0;
            o[nf][2] *= c1; o[nf][3] *= c1;
        }

        // ---- O += P V : extract P A-frags via shfl (acc->A layout) ----
        const int sl = (g << 2) + (tg >> 1);
        const bool odd = (tg & 1) != 0;
#pragma unroll
        for (int ks = 0; ks < 16; ks++) {
            const int kb = ks * 8;
            float v00 = __shfl_sync(0xffffffffu, p[ks][0], sl);
            float v01 = __shfl_sync(0xffffffffu, p[ks][1], sl);
            float v10 = __shfl_sync(0xffffffffu, p[ks][2], sl);
            float v11 = __shfl_sync(0xffffffffu, p[ks][3], sl);
            float v20 = __shfl_sync(0xffffffffu, p[ks][0], sl + 2);
            float v21 = __shfl_sync(0xffffffffu, p[ks][1], sl + 2);
            float v30 = __shfl_sync(0xffffffffu, p[ks][2], sl + 2);
            float v31 = __shfl_sync(0xffffffffu, p[ks][3], sl + 2);
            float a0 = odd ? v01 : v00;
            float a1 = odd ? v11 : v10;
            float a2 = odd ? v21 : v20;
            float a3 = odd ? v31 : v30;
            uint32_t ah0 = __float_as_uint(a0), al0 = tf32_lo(a0);
            uint32_t ah1 = __float_as_uint(a1), al1 = tf32_lo(a1);
            uint32_t ah2 = __float_as_uint(a2), al2 = tf32_lo(a2);
            uint32_t ah3 = __float_as_uint(a3), al3 = tf32_lo(a3);
#pragma unroll
            for (int nf = 0; nf < 8; nf++) {
                const int n = nf * 8 + g;
                float b0 = VT[n * VT_PITCH + kb + tg    ];
                float b1 = VT[n * VT_PITCH + kb + tg + 4];
                uint32_t bh0 = __float_as_uint(b0), bh1 = __float_as_uint(b1);
                uint32_t bl0 = tf32_lo(b0),         bl1 = tf32_lo(b1);
                mma_tf32(o[nf][0], o[nf][1], o[nf][2], o[nf][3],
                         ah0, ah1, ah2, ah3, bh0, bh1);
                mma_tf32(o[nf][0], o[nf][1], o[nf][2], o[nf][3],
                         al0, al1, al2, al3, bh0, bh1);
                mma_tf32(o[nf][0], o[nf][1], o[nf][2], o[nf][3],
                         ah0, ah1, ah2, ah3, bl0, bl1);
            }
        }
        __syncthreads();   // all reads done before next iter's cp.async overwrites
    }

    // ---- epilogue ----
    const float il0 = 1.f / l0, il1 = 1.f / l1;
    const size_t r0 = (size_t)(bS + i0 + warpM + g);
    const size_t r1 = r0 + 8;
#pragma unroll
    for (int nf = 0; nf < 8; nf++) {
        const int col = zh * HDIM + nf * 8 + 2 * tg;
        float2 o0 = { o[nf][0] * il0, o[nf][1] * il0 };
        float2 o1 = { o[nf][2] * il1, o[nf][3] * il1 };
        *reinterpret_cast<float2*>(gout + r0 * EMBED + col) = o0;
        *reinterpret_cast<float2*>(gout + r1 * EMBED + col) = o1;
    }
}

// ---------------- transposes -------------------------------------------------
__global__ void transpose_w(const float* __restrict__ in, float* __restrict__ out,
                            int R, int C)
{
    __shared__ float t[32][33];
    const int c0 = blockIdx.x * 32, r0 = blockIdx.y * 32;
    const int x = threadIdx.x, y = threadIdx.y;
#pragma unroll
    for (int i = 0; i < 32; i += 8) t[y + i][x] = in[(size_t)(r0 + y + i) * C + c0 + x];
    __syncthreads();
#pragma unroll
    for (int i = 0; i < 32; i += 8) out[(size_t)(c0 + y + i) * R + r0 + x] = t[x][y + i];
}

// gvT[pair][d][j] = V[(b*SEQ+j)*EMBED + h*HDIM + d]
__global__ void transpose_v(const float* __restrict__ v, float* __restrict__ vt)
{
    __shared__ float t[32][33];
    const int z = blockIdx.z, zb = z >> 4, zh = z & 15;
    const int j0 = blockIdx.x * 32, d0 = blockIdx.y * 32;
    const int x = threadIdx.x, y = threadIdx.y;
    const float* in = v + (size_t)zb * SEQ * EMBED + (size_t)zh * HDIM;
    float* out = vt + (size_t)z * HDIM * SEQ;
#pragma unroll
    for (int i = 0; i < 32; i += 8) t[y + i][x] = in[(size_t)(j0 + y + i) * EMBED + d0 + x];
    __syncthreads();
#pragma unroll
    for (int i = 0; i < 32; i += 8) out[(size_t)(d0 + y + i) * SEQ + j0 + x] = t[x][y + i];
}

// ---------------- launch ------------------------------------------------------
extern "C" void kernel_launch(void* const* d_in, const int* in_sizes, int n_in,
                              void* d_out, int out_size)
{
    const float* X  = (const float*)d_in[0];
    const float* Wq = (const float*)d_in[1];
    const float* bq = (const float*)d_in[2];
    const float* Wk = (const float*)d_in[3];
    const float* bk = (const float*)d_in[4];
    const float* Wv = (const float*)d_in[5];
    const float* bv = (const float*)d_in[6];
    const float* Wo = (const float*)d_in[7];
    const float* bo = (const float*)d_in[8];
    float* out = (float*)d_out;

    float *pq, *pk, *pv, *pa, *pvT, *pwqT, *pwkT, *pwvT, *pwoT;
    cudaGetSymbolAddress((void**)&pq,   g_q);
    cudaGetSymbolAddress((void**)&pk,   g_k);
    cudaGetSymbolAddress((void**)&pv,   g_v);
    cudaGetSymbolAddress((void**)&pa,   g_attn);
    cudaGetSymbolAddress((void**)&pvT,  g_vT);
    cudaGetSymbolAddress((void**)&pwqT, g_wqT);
    cudaGetSymbolAddress((void**)&pwkT, g_wkT);
    cudaGetSymbolAddress((void**)&pwvT, g_wvT);
    cudaGetSymbolAddress((void**)&pwoT, g_woT);

    static bool attr_done = false;
    if (!attr_done) {
        cudaFuncSetAttribute(flash_kernel,
                             cudaFuncAttributeMaxDynamicSharedMemorySize, FLASH_SMEM);
        attr_done = true;
    }

    const dim3 tb(32, 8);
    transpose_w<<<dim3(QKDIM / 32, EMBED / 32), tb>>>(Wq, pwqT, EMBED, QKDIM);
    transpose_w<<<dim3(QKDIM / 32, EMBED / 32), tb>>>(Wk, pwkT, EMBED, QKDIM);
    transpose_w<<<dim3(EMBED / 32, EMBED / 32), tb>>>(Wv, pwvT, EMBED, EMBED);
    transpose_w<<<dim3(EMBED / 32, EMBED / 32), tb>>>(Wo, pwoT, EMBED, EMBED);

    // Q/K/V projections
    tc_gemm<<<dim3(QKDIM / 128, BSROWS / 128), 256>>>(
        X, EMBED, pwqT, EMBED, pq, QKDIM, EMBED, bq, 1.f);
    tc_gemm<<<dim3(QKDIM / 128, BSROWS / 128), 256>>>(
        X, EMBED, pwkT, EMBED, pk, QKDIM, EMBED, bk, 1.f);
    tc_gemm<<<dim3(EMBED / 128, BSROWS / 128), 256>>>(
        X, EMBED, pwvT, EMBED, pv, EMBED, EMBED, bv, 1.f);

    transpose_v<<<dim3(SEQ / 32, HDIM / 32, NPAIRS), tb>>>(pv, pvT);

    // fused attention
    flash_kernel<<<dim3(SEQ / 128, NPAIRS), 256, FLASH_SMEM>>>(pq, pk, pvT, pa);

    // final projection
    tc_gemm<<<dim3(EMBED / 128, BSROWS / 128), 256>>>(
        pa, EMBED, pwoT, EMBED, out, EMBED, EMBED, bo, 1.f);
}

// round 9
// speedup vs baseline: 3.8397x; 1.4958x over previous
#include <cuda_runtime.h>
#include <cstdint>

#define EMBED   1024
#define NHEADS  16
#define RANK    32
#define HDIM    64
#define BATCH   2
#define SEQ     2048
#define BSROWS  (BATCH*SEQ)        /* 4096 */
#define QKDIM   (NHEADS*RANK)      /* 512  */
#define NPAIRS  (BATCH*NHEADS)     /* 32   */
#define SM_SCALE 0.17677669529663687f

// ---------------- scratch (__device__ globals: allocation-free rule) --------
__device__ float g_q   [BSROWS * QKDIM];
__device__ float g_k   [BSROWS * QKDIM];
__device__ float g_v   [BSROWS * EMBED];
__device__ float g_attn[BSROWS * EMBED];
__device__ float g_vT  [NPAIRS * HDIM * SEQ];
__device__ float g_wqT [QKDIM * EMBED];
__device__ float g_wkT [QKDIM * EMBED];
__device__ float g_wvT [EMBED * EMBED];
__device__ float g_woT [EMBED * EMBED];

// ---------------- bf16x2 helpers ---------------------------------------------
// pack two fp32 (e0 = lower k index -> low 16 bits) into bf16x2
__device__ __forceinline__ uint32_t bf_hi_pack(float e0, float e1) {
    uint32_t r;
    asm("cvt.rn.bf16x2.f32 %0, %1, %2;" : "=r"(r) : "f"(e1), "f"(e0));
    return r;
}
// residual pack: bf16x2 of (e - float(hi))
__device__ __forceinline__ uint32_t bf_lo_pack(uint32_t hi, float e0, float e1) {
    float h0 = __uint_as_float(hi << 16);
    float h1 = __uint_as_float(hi & 0xFFFF0000u);
    uint32_t r;
    asm("cvt.rn.bf16x2.f32 %0, %1, %2;" : "=r"(r) : "f"(e1 - h1), "f"(e0 - h0));
    return r;
}

// ---------------- m16n8k16 bf16 mma ------------------------------------------
__device__ __forceinline__ void mma_bf16(float& c0, float& c1, float& c2, float& c3,
                                         uint32_t a0, uint32_t a1, uint32_t a2, uint32_t a3,
                                         uint32_t b0, uint32_t b1)
{
    asm volatile(
        "mma.sync.aligned.m16n8k16.row.col.f32.bf16.bf16.f32 "
        "{%0,%1,%2,%3}, {%4,%5,%6,%7}, {%8,%9}, {%0,%1,%2,%3};"
        : "+f"(c0), "+f"(c1), "+f"(c2), "+f"(c3)
        : "r"(a0), "r"(a1), "r"(a2), "r"(a3), "r"(b0), "r"(b1));
}

// ---------------- cp.async helpers ------------------------------------------
__device__ __forceinline__ uint32_t smem_u32(const void* p) {
    uint32_t a;
    asm("{ .reg .u64 t; cvta.to.shared.u64 t, %1; cvt.u32.u64 %0, t; }" : "=r"(a) : "l"(p));
    return a;
}
__device__ __forceinline__ void cp16(uint32_t dst, const void* src) {
    asm volatile("cp.async.cg.shared.global [%0], [%1], 16;" :: "r"(dst), "l"(src));
}
#define CP_COMMIT() asm volatile("cp.async.commit_group;" ::: "memory")
#define CP_WAIT(n)  asm volatile("cp.async.wait_group %0;" :: "n"(n) : "memory")

// ---------------- generic bf16x2 HMMA GEMM (projections) ---------------------
// C[m][n] = uscale * ( sum_k A[m][k]*B[n][k] + bias[n] )
// A: [M,K] row-major; B: [N,K] row-major. Tile 128x128, K-tile 32, 256 thr.
// Smem holds bf16x2 hi/lo planes: u32[128][20] each (k pairs packed).
__global__ __launch_bounds__(256, 2) void tc_gemm(
    const float* __restrict__ A, int lda,
    const float* __restrict__ B, int ldb,
    float* __restrict__ C, int ldc,
    int K, const float* __restrict__ bias, float uscale)
{
    __shared__ __align__(8) uint32_t Ahi[128 * 20], Alo[128 * 20];
    __shared__ __align__(8) uint32_t Bhi[128 * 20], Blo[128 * 20];

    const int tid  = threadIdx.x;
    const int wid  = tid >> 5;
    const int lane = tid & 31;
    const int g    = lane >> 2;
    const int tg   = lane & 3;
    const int m0 = blockIdx.y * 128, n0 = blockIdx.x * 128;
    const int warpM = (wid >> 2) * 64;
    const int warpN = (wid & 3) * 32;

    const int ar = tid >> 1;          // load row 0..127
    const int ah = (tid & 1) * 16;    // float col base

    float acc[4][4][4];
#pragma unroll
    for (int i = 0; i < 4; i++)
#pragma unroll
        for (int j = 0; j < 4; j++)
#pragma unroll
            for (int r = 0; r < 4; r++) acc[i][j][r] = 0.f;

    const int nk = K >> 5;
    for (int kt = 0; kt < nk; kt++) {
        const int k0 = kt << 5;
        {
            const float* src = A + (size_t)(m0 + ar) * lda + k0 + ah;
#pragma unroll
            for (int c = 0; c < 4; c++) {
                float4 v = *reinterpret_cast<const float4*>(src + c * 4);
                uint32_t h0 = bf_hi_pack(v.x, v.y), h1 = bf_hi_pack(v.z, v.w);
                uint32_t l0 = bf_lo_pack(h0, v.x, v.y), l1 = bf_lo_pack(h1, v.z, v.w);
                const int col = (ah >> 1) + 2 * c;
                *reinterpret_cast<uint2*>(&Ahi[ar * 20 + col]) = make_uint2(h0, h1);
                *reinterpret_cast<uint2*>(&Alo[ar * 20 + col]) = make_uint2(l0, l1);
            }
        }
        {
            const float* src = B + (size_t)(n0 + ar) * ldb + k0 + ah;
#pragma unroll
            for (int c = 0; c < 4; c++) {
                float4 v = *reinterpret_cast<const float4*>(src + c * 4);
                uint32_t h0 = bf_hi_pack(v.x, v.y), h1 = bf_hi_pack(v.z, v.w);
                uint32_t l0 = bf_lo_pack(h0, v.x, v.y), l1 = bf_lo_pack(h1, v.z, v.w);
                const int col = (ah >> 1) + 2 * c;
                *reinterpret_cast<uint2*>(&Bhi[ar * 20 + col]) = make_uint2(h0, h1);
                *reinterpret_cast<uint2*>(&Blo[ar * 20 + col]) = make_uint2(l0, l1);
            }
        }
        __syncthreads();

        // 2 k16-steps per 32-tile
#pragma unroll
        for (int ks = 0; ks < 2; ks++) {
            const int kb = ks * 8;   // u32 col base
            uint32_t ah_[4][4], al_[4][4];
#pragma unroll
            for (int i = 0; i < 4; i++) {
                const int r = warpM + i * 16 + g;
                ah_[i][0] = Ahi[r * 20 + kb + tg];
                ah_[i][1] = Ahi[(r + 8) * 20 + kb + tg];
                ah_[i][2] = Ahi[r * 20 + kb + 4 + tg];
                ah_[i][3] = Ahi[(r + 8) * 20 + kb + 4 + tg];
                al_[i][0] = Alo[r * 20 + kb + tg];
                al_[i][1] = Alo[(r + 8) * 20 + kb + tg];
                al_[i][2] = Alo[r * 20 + kb + 4 + tg];
                al_[i][3] = Alo[(r + 8) * 20 + kb + 4 + tg];
            }
#pragma unroll
            for (int j = 0; j < 4; j++) {
                const int n = warpN + j * 8 + g;
                uint32_t bh0 = Bhi[n * 20 + kb + tg];
                uint32_t bh1 = Bhi[n * 20 + kb + 4 + tg];
                uint32_t bl0 = Blo[n * 20 + kb + tg];
                uint32_t bl1 = Blo[n * 20 + kb + 4 + tg];
#pragma unroll
                for (int i = 0; i < 4; i++) {
                    mma_bf16(acc[i][j][0], acc[i][j][1], acc[i][j][2], acc[i][j][3],
                             ah_[i][0], ah_[i][1], ah_[i][2], ah_[i][3], bh0, bh1);
                    mma_bf16(acc[i][j][0], acc[i][j][1], acc[i][j][2], acc[i][j][3],
                             al_[i][0], al_[i][1], al_[i][2], al_[i][3], bh0, bh1);
                    mma_bf16(acc[i][j][0], acc[i][j][1], acc[i][j][2], acc[i][j][3],
                             ah_[i][0], ah_[i][1], ah_[i][2], ah_[i][3], bl0, bl1);
                }
            }
        }
        __syncthreads();
    }

#pragma unroll
    for (int i = 0; i < 4; i++) {
        const int r0 = m0 + warpM + i * 16 + g;
        const int r1 = r0 + 8;
#pragma unroll
        for (int j = 0; j < 4; j++) {
            const int col = n0 + warpN + j * 8 + 2 * tg;
            float b0 = bias ? bias[col] : 0.f;
            float b1 = bias ? bias[col + 1] : 0.f;
            float2 o0, o1;
            o0.x = (acc[i][j][0] + b0) * uscale;
            o0.y = (acc[i][j][1] + b1) * uscale;
            o1.x = (acc[i][j][2] + b0) * uscale;
            o1.y = (acc[i][j][3] + b1) * uscale;
            *reinterpret_cast<float2*>(C + (size_t)r0 * ldc + col) = o0;
            *reinterpret_cast<float2*>(C + (size_t)r1 * ldc + col) = o1;
        }
    }
}

// ---------------- fused flash attention (bf16x2) -----------------------------
// Grid (SEQ/128, NPAIRS). 256 threads = 8 warps; warp w owns rows w*16..w*16+15
// across all 128 j-cols. cp.async double-buffered fp32 tiles; per-tile convert
// pass into single-buffered bf16x2 hi/lo planes (reused by all 8 warps).
#define KF32_BUF  16384                  /* 128*32*4  */
#define VF32_BUF  32768                  /* 64*128*4  */
#define OFF_V32   (2*KF32_BUF)           /* 32768     */
#define OFF_KHI   (OFF_V32 + 2*VF32_BUF) /* 98304     */
#define OFF_KLO   (OFF_KHI + 10240)      /* 128*20*4  */
#define OFF_VHI   (OFF_KLO + 10240)
#define OFF_VLO   (OFF_VHI + 17408)      /* 64*68*4   */
#define FLASH_SMEM (OFF_VLO + 17408)     /* 153600    */

__global__ __launch_bounds__(256, 1) void flash_kernel(
    const float* __restrict__ gq, const float* __restrict__ gk,
    const float* __restrict__ gvT, float* __restrict__ gout)
{
    extern __shared__ char sm[];
    const uint32_t sb = smem_u32(sm);
    uint32_t* Khi = reinterpret_cast<uint32_t*>(sm + OFF_KHI);
    uint32_t* Klo = reinterpret_cast<uint32_t*>(sm + OFF_KLO);
    uint32_t* Vhi = reinterpret_cast<uint32_t*>(sm + OFF_VHI);
    uint32_t* Vlo = reinterpret_cast<uint32_t*>(sm + OFF_VLO);

    const int tid  = threadIdx.x;
    const int wid  = tid >> 5;
    const int lane = tid & 31;
    const int g    = lane >> 2;
    const int tg   = lane & 3;
    const int z  = blockIdx.y, zb = z >> 4, zh = z & 15;
    const int i0 = blockIdx.x * 128;
    const long bS = (long)zb * SEQ;
    const int hq = zh * RANK;
    const size_t vbase = (size_t)z * HDIM * SEQ;
    const int warpM = wid * 16;

    // ---- Q fragments resident (scale folded, bf16x2 split): 2 k16-chunks ----
    uint32_t qhi[2][4], qlo[2][4];
    {
        const float* q0 = gq + (size_t)(bS + i0 + warpM + g) * QKDIM + hq;
        const float* q1 = q0 + 8 * QKDIM;
#pragma unroll
        for (int ch = 0; ch < 2; ch++) {
            const int kb = ch * 16;
            float v00 = q0[kb + 2 * tg    ] * SM_SCALE;
            float v01 = q0[kb + 2 * tg + 1] * SM_SCALE;
            float v10 = q1[kb + 2 * tg    ] * SM_SCALE;
            float v11 = q1[kb + 2 * tg + 1] * SM_SCALE;
            float v20 = q0[kb + 8 + 2 * tg    ] * SM_SCALE;
            float v21 = q0[kb + 8 + 2 * tg + 1] * SM_SCALE;
            float v30 = q1[kb + 8 + 2 * tg    ] * SM_SCALE;
            float v31 = q1[kb + 8 + 2 * tg + 1] * SM_SCALE;
            qhi[ch][0] = bf_hi_pack(v00, v01); qlo[ch][0] = bf_lo_pack(qhi[ch][0], v00, v01);
            qhi[ch][1] = bf_hi_pack(v10, v11); qlo[ch][1] = bf_lo_pack(qhi[ch][1], v10, v11);
            qhi[ch][2] = bf_hi_pack(v20, v21); qlo[ch][2] = bf_lo_pack(qhi[ch][2], v20, v21);
            qhi[ch][3] = bf_hi_pack(v30, v31); qlo[ch][3] = bf_lo_pack(qhi[ch][3], v30, v31);
        }
    }

    // ---- cp.async tile loader (fp32) ----
    auto load_tiles = [&](int buf, int j0) {
#pragma unroll
        for (int t = 0; t < 4; t++) {           // K: 1024 16B chunks
            int c = tid + t * 256;
            int row = c >> 3, c16 = c & 7;
            cp16(sb + buf * KF32_BUF + c * 16,
                 gk + (size_t)(bS + j0 + row) * QKDIM + hq + c16 * 4);
        }
#pragma unroll
        for (int t = 0; t < 8; t++) {           // Vt: 2048 16B chunks
            int c = tid + t * 256;
            int d = c >> 5, c16 = c & 31;
            cp16(sb + OFF_V32 + buf * VF32_BUF + c * 16,
                 gvT + vbase + (size_t)d * SEQ + j0 + c16 * 4);
        }
        CP_COMMIT();
    };

    // ---- fp32 tile -> bf16x2 planes ----
    auto convert_tiles = [&](int buf) {
        const float4* kf = reinterpret_cast<const float4*>(sm + buf * KF32_BUF);
#pragma unroll
        for (int t = 0; t < 4; t++) {
            int c = tid + t * 256;
            int row = c >> 3, q = c & 7;
            float4 v = kf[c];
            uint32_t h0 = bf_hi_pack(v.x, v.y), h1 = bf_hi_pack(v.z, v.w);
            uint32_t l0 = bf_lo_pack(h0, v.x, v.y), l1 = bf_lo_pack(h1, v.z, v.w);
            *reinterpret_cast<uint2*>(&Khi[row * 20 + 2 * q]) = make_uint2(h0, h1);
            *reinterpret_cast<uint2*>(&Klo[row * 20 + 2 * q]) = make_uint2(l0, l1);
        }
        const float4* vf = reinterpret_cast<const float4*>(sm + OFF_V32 + buf * VF32_BUF);
#pragma unroll
        for (int t = 0; t < 8; t++) {
            int c = tid + t * 256;
            int row = c >> 5, q = c & 31;
            float4 v = vf[c];
            uint32_t h0 = bf_hi_pack(v.x, v.y), h1 = bf_hi_pack(v.z, v.w);
            uint32_t l0 = bf_lo_pack(h0, v.x, v.y), l1 = bf_lo_pack(h1, v.z, v.w);
            *reinterpret_cast<uint2*>(&Vhi[row * 68 + 2 * q]) = make_uint2(h0, h1);
            *reinterpret_cast<uint2*>(&Vlo[row * 68 + 2 * q]) = make_uint2(l0, l1);
        }
    };

    float o[8][4];
#pragma unroll
    for (int nf = 0; nf < 8; nf++)
#pragma unroll
        for (int r = 0; r < 4; r++) o[nf][r] = 0.f;
    float m0r = -1e30f, m1r = -1e30f, l0 = 0.f, l1 = 0.f;

    load_tiles(0, 0);

    for (int jt = 0; jt < 16; jt++) {
        if (jt < 15) load_tiles((jt + 1) & 1, (jt + 1) * 128);
        if (jt < 15) { CP_WAIT(1); } else { CP_WAIT(0); }
        __syncthreads();                 // fp32 tile ready; planes free (prev compute done)
        convert_tiles(jt & 1);
        __syncthreads();                 // planes ready

        // ---- S = Q K^T ----
        float p[16][4];
#pragma unroll
        for (int jf = 0; jf < 16; jf++)
#pragma unroll
            for (int r = 0; r < 4; r++) p[jf][r] = 0.f;

#pragma unroll
        for (int ch = 0; ch < 2; ch++) {
            const int kb = ch * 8;
#pragma unroll
            for (int jf = 0; jf < 16; jf++) {
                const int n = jf * 8 + g;
                uint32_t bh0 = Khi[n * 20 + kb + tg];
                uint32_t bh1 = Khi[n * 20 + kb + 4 + tg];
                uint32_t bl0 = Klo[n * 20 + kb + tg];
                uint32_t bl1 = Klo[n * 20 + kb + 4 + tg];
                mma_bf16(p[jf][0], p[jf][1], p[jf][2], p[jf][3],
                         qhi[ch][0], qhi[ch][1], qhi[ch][2], qhi[ch][3], bh0, bh1);
                mma_bf16(p[jf][0], p[jf][1], p[jf][2], p[jf][3],
                         qlo[ch][0], qlo[ch][1], qlo[ch][2], qlo[ch][3], bh0, bh1);
                mma_bf16(p[jf][0], p[jf][1], p[jf][2], p[jf][3],
                         qhi[ch][0], qhi[ch][1], qhi[ch][2], qhi[ch][3], bl0, bl1);
            }
        }

        // ---- online softmax (rows g and g+8) ----
        float mx0 = -1e30f, mx1 = -1e30f;
#pragma unroll
        for (int jf = 0; jf < 16; jf++) {
            mx0 = fmaxf(mx0, fmaxf(p[jf][0], p[jf][1]));
            mx1 = fmaxf(mx1, fmaxf(p[jf][2], p[jf][3]));
        }
        mx0 = fmaxf(mx0, __shfl_xor_sync(0xffffffffu, mx0, 1));
        mx0 = fmaxf(mx0, __shfl_xor_sync(0xffffffffu, mx0, 2));
        mx1 = fmaxf(mx1, __shfl_xor_sync(0xffffffffu, mx1, 1));
        mx1 = fmaxf(mx1, __shfl_xor_sync(0xffffffffu, mx1, 2));
        float mn0 = fmaxf(m0r, mx0), mn1 = fmaxf(m1r, mx1);
        float c0 = __expf(m0r - mn0), c1 = __expf(m1r - mn1);
        float s0 = 0.f, s1 = 0.f;
#pragma unroll
        for (int jf = 0; jf < 16; jf++) {
            p[jf][0] = __expf(p[jf][0] - mn0); s0 += p[jf][0];
            p[jf][1] = __expf(p[jf][1] - mn0); s0 += p[jf][1];
            p[jf][2] = __expf(p[jf][2] - mn1); s1 += p[jf][2];
            p[jf][3] = __expf(p[jf][3] - mn1); s1 += p[jf][3];
        }
        s0 += __shfl_xor_sync(0xffffffffu, s0, 1);
        s0 += __shfl_xor_sync(0xffffffffu, s0, 2);
        s1 += __shfl_xor_sync(0xffffffffu, s1, 1);
        s1 += __shfl_xor_sync(0xffffffffu, s1, 2);
        l0 = l0 * c0 + s0; l1 = l1 * c1 + s1;
        m0r = mn0; m1r = mn1;
#pragma unroll
        for (int nf = 0; nf < 8; nf++) {
            o[nf][0] *= c0; o[nf][1] *= c0;
            o[nf][2] *= c1; o[nf][3] *= c1;
        }

        // ---- O += P V : m16n8k16 A-frag == two adjacent acc blocks (no shfl) ----
#pragma unroll
        for (int c = 0; c < 8; c++) {
            uint32_t a0h = bf_hi_pack(p[2 * c][0],     p[2 * c][1]);
            uint32_t a1h = bf_hi_pack(p[2 * c][2],     p[2 * c][3]);
            uint32_t a2h = bf_hi_pack(p[2 * c + 1][0], p[2 * c + 1][1]);
            uint32_t a3h = bf_hi_pack(p[2 * c + 1][2], p[2 * c + 1][3]);
            uint32_t a0l = bf_lo_pack(a0h, p[2 * c][0],     p[2 * c][1]);
            uint32_t a1l = bf_lo_pack(a1h, p[2 * c][2],     p[2 * c][3]);
            uint32_t a2l = bf_lo_pack(a2h, p[2 * c + 1][0], p[2 * c + 1][1]);
            uint32_t a3l = bf_lo_pack(a3h, p[2 * c + 1][2], p[2 * c + 1][3]);
            const int kb = c * 8;
#pragma unroll
            for (int nf = 0; nf < 8; nf++) {
                const int n = nf * 8 + g;
                uint32_t bh0 = Vhi[n * 68 + kb + tg];
                uint32_t bh1 = Vhi[n * 68 + kb + 4 + tg];
                uint32_t bl0 = Vlo[n * 68 + kb + tg];
                uint32_t bl1 = Vlo[n * 68 + kb + 4 + tg];
                mma_bf16(o[nf][0], o[nf][1], o[nf][2], o[nf][3],
                         a0h, a1h, a2h, a3h, bh0, bh1);
                mma_bf16(o[nf][0], o[nf][1], o[nf][2], o[nf][3],
                         a0l, a1l, a2l, a3l, bh0, bh1);
                mma_bf16(o[nf][0], o[nf][1], o[nf][2], o[nf][3],
                         a0h, a1h, a2h, a3h, bl0, bl1);
            }
        }
        __syncthreads();   // planes/fp32 reads done before next iter overwrites
    }

    // ---- epilogue ----
    const float il0 = 1.f / l0, il1 = 1.f / l1;
    const size_t r0 = (size_t)(bS + i0 + warpM + g);
    const size_t r1 = r0 + 8;
#pragma unroll
    for (int nf = 0; nf < 8; nf++) {
        const int col = zh * HDIM + nf * 8 + 2 * tg;
        float2 o0 = { o[nf][0] * il0, o[nf][1] * il0 };
        float2 o1 = { o[nf][2] * il1, o[nf][3] * il1 };
        *reinterpret_cast<float2*>(gout + r0 * EMBED + col) = o0;
        *reinterpret_cast<float2*>(gout + r1 * EMBED + col) = o1;
    }
}

// ---------------- transposes -------------------------------------------------
__global__ void transpose_w(const float* __restrict__ in, float* __restrict__ out,
                            int R, int C)
{
    __shared__ float t[32][33];
    const int c0 = blockIdx.x * 32, r0 = blockIdx.y * 32;
    const int x = threadIdx.x, y = threadIdx.y;
#pragma unroll
    for (int i = 0; i < 32; i += 8) t[y + i][x] = in[(size_t)(r0 + y + i) * C + c0 + x];
    __syncthreads();
#pragma unroll
    for (int i = 0; i < 32; i += 8) out[(size_t)(c0 + y + i) * R + r0 + x] = t[x][y + i];
}

// gvT[pair][d][j] = V[(b*SEQ+j)*EMBED + h*HDIM + d]
__global__ void transpose_v(const float* __restrict__ v, float* __restrict__ vt)
{
    __shared__ float t[32][33];
    const int z = blockIdx.z, zb = z >> 4, zh = z & 15;
    const int j0 = blockIdx.x * 32, d0 = blockIdx.y * 32;
    const int x = threadIdx.x, y = threadIdx.y;
    const float* in = v + (size_t)zb * SEQ * EMBED + (size_t)zh * HDIM;
    float* out = vt + (size_t)z * HDIM * SEQ;
#pragma unroll
    for (int i = 0; i < 32; i += 8) t[y + i][x] = in[(size_t)(j0 + y + i) * EMBED + d0 + x];
    __syncthreads();
#pragma unroll
    for (int i = 0; i < 32; i += 8) out[(size_t)(d0 + y + i) * SEQ + j0 + x] = t[x][y + i];
}

// ---------------- launch ------------------------------------------------------
extern "C" void kernel_launch(void* const* d_in, const int* in_sizes, int n_in,
                              void* d_out, int out_size)
{
    const float* X  = (const float*)d_in[0];
    const float* Wq = (const float*)d_in[1];
    const float* bq = (const float*)d_in[2];
    const float* Wk = (const float*)d_in[3];
    const float* bk = (const float*)d_in[4];
    const float* Wv = (const float*)d_in[5];
    const float* bv = (const float*)d_in[6];
    const float* Wo = (const float*)d_in[7];
    const float* bo = (const float*)d_in[8];
    float* out = (float*)d_out;

    float *pq, *pk, *pv, *pa, *pvT, *pwqT, *pwkT, *pwvT, *pwoT;
    cudaGetSymbolAddress((void**)&pq,   g_q);
    cudaGetSymbolAddress((void**)&pk,   g_k);
    cudaGetSymbolAddress((void**)&pv,   g_v);
    cudaGetSymbolAddress((void**)&pa,   g_attn);
    cudaGetSymbolAddress((void**)&pvT,  g_vT);
    cudaGetSymbolAddress((void**)&pwqT, g_wqT);
    cudaGetSymbolAddress((void**)&pwkT, g_wkT);
    cudaGetSymbolAddress((void**)&pwvT, g_wvT);
    cudaGetSymbolAddress((void**)&pwoT, g_woT);

    static bool attr_done = false;
    if (!attr_done) {
        cudaFuncSetAttribute(flash_kernel,
                             cudaFuncAttributeMaxDynamicSharedMemorySize, FLASH_SMEM);
        attr_done = true;
    }

    const dim3 tb(32, 8);
    transpose_w<<<dim3(QKDIM / 32, EMBED / 32), tb>>>(Wq, pwqT, EMBED, QKDIM);
    transpose_w<<<dim3(QKDIM / 32, EMBED / 32), tb>>>(Wk, pwkT, EMBED, QKDIM);
    transpose_w<<<dim3(EMBED / 32, EMBED / 32), tb>>>(Wv, pwvT, EMBED, EMBED);
    transpose_w<<<dim3(EMBED / 32, EMBED / 32), tb>>>(Wo, pwoT, EMBED, EMBED);

    // Q/K/V projections
    tc_gemm<<<dim3(QKDIM / 128, BSROWS / 128), 256>>>(
        X, EMBED, pwqT, EMBED, pq, QKDIM, EMBED, bq, 1.f);
    tc_gemm<<<dim3(QKDIM / 128, BSROWS / 128), 256>>>(
        X, EMBED, pwkT, EMBED, pk, QKDIM, EMBED, bk, 1.f);
    tc_gemm<<<dim3(EMBED / 128, BSROWS / 128), 256>>>(
        X, EMBED, pwvT, EMBED, pv, EMBED, EMBED, bv, 1.f);

    transpose_v<<<dim3(SEQ / 32, HDIM / 32, NPAIRS), tb>>>(pv, pvT);

    // fused attention
    flash_kernel<<<dim3(SEQ / 128, NPAIRS), 256, FLASH_SMEM>>>(pq, pk, pvT, pa);

    // final projection
    tc_gemm<<<dim3(EMBED / 128, BSROWS / 128), 256>>>(
        pa, EMBED, pwoT, EMBED, out, EMBED, EMBED, bo, 1.f);
}